// round 1
// baseline (speedup 1.0000x reference)
#include <cuda_runtime.h>
#include <math.h>
#include <float.h>

#define N_ROWS 8192
#define M_ROWS 16384
#define D_DIM  512
#define K_TOP  10
#define EPSF   1e-8f

// ---------------- device scratch (no allocations allowed) ----------------
__device__ float g_dist[(size_t)N_ROWS * (size_t)M_ROWS];  // 512 MB distance matrix
__device__ float g_x2[N_ROWS];
__device__ float g_m2[M_ROWS];
__device__ float g_mean[N_ROWS];
__device__ int   g_idx0[N_ROWS];
__device__ int   g_dmin_bits;
__device__ int   g_dmax_bits;

// ---------------- init (reset per launch; graph-replay safe) ----------------
__global__ void init_kernel() {
    g_dmin_bits = 0x7f7fffff;  // FLT_MAX
    g_dmax_bits = 0;           // all means are > 0
}

// ---------------- row sum-of-squares: 1 block (128 thr) per row of 512 ----------------
__global__ __launch_bounds__(128) void rowsumsq(const float* __restrict__ src, int which) {
    float* dst = which ? g_m2 : g_x2;
    int row = blockIdx.x;
    const float4* p = (const float4*)(src + (size_t)row * D_DIM);
    float4 v = p[threadIdx.x];
    float s = v.x * v.x + v.y * v.y + v.z * v.z + v.w * v.w;
    #pragma unroll
    for (int o = 16; o; o >>= 1) s += __shfl_down_sync(0xffffffffu, s, o);
    __shared__ float ws[4];
    if ((threadIdx.x & 31) == 0) ws[threadIdx.x >> 5] = s;
    __syncthreads();
    if (threadIdx.x == 0) dst[row] = ws[0] + ws[1] + ws[2] + ws[3];
}

// ---------------- SGEMM -> euclidean distance matrix ----------------
// C tile 128x128, K tile 16, 256 threads, 8x8 per-thread register tile.
__global__ __launch_bounds__(256) void gemm_dist(const float* __restrict__ A,   // features [N,D]
                                                 const float* __restrict__ B) { // memory   [M,D]
    __shared__ float As[16][128];
    __shared__ float Bs[16][128];

    const int bm = blockIdx.y * 128;   // feature rows
    const int bn = blockIdx.x * 128;   // memory rows
    const int tid = threadIdx.x;
    const int tr = (tid >> 4) << 3;    // 0..120 step 8 (rows)
    const int tc = (tid & 15) << 3;    // 0..120 step 8 (cols)

    float acc[8][8];
    #pragma unroll
    for (int m = 0; m < 8; m++)
        #pragma unroll
        for (int n = 0; n < 8; n++) acc[m][n] = 0.0f;

    for (int k0 = 0; k0 < D_DIM; k0 += 16) {
        #pragma unroll
        for (int i = 0; i < 2; i++) {
            int idx = tid + i * 256;          // 0..511
            int row = idx >> 2;               // 0..127
            int c4  = (idx & 3) << 2;         // 0,4,8,12
            float4 va = *(const float4*)(A + (size_t)(bm + row) * D_DIM + k0 + c4);
            As[c4 + 0][row] = va.x; As[c4 + 1][row] = va.y;
            As[c4 + 2][row] = va.z; As[c4 + 3][row] = va.w;
            float4 vb = *(const float4*)(B + (size_t)(bn + row) * D_DIM + k0 + c4);
            Bs[c4 + 0][row] = vb.x; Bs[c4 + 1][row] = vb.y;
            Bs[c4 + 2][row] = vb.z; Bs[c4 + 3][row] = vb.w;
        }
        __syncthreads();

        #pragma unroll
        for (int k = 0; k < 16; k++) {
            float a[8], b[8];
            #pragma unroll
            for (int m = 0; m < 8; m++) a[m] = As[k][tr + m];
            #pragma unroll
            for (int n = 0; n < 8; n++) b[n] = Bs[k][tc + n];
            #pragma unroll
            for (int m = 0; m < 8; m++)
                #pragma unroll
                for (int n = 0; n < 8; n++) acc[m][n] = fmaf(a[m], b[n], acc[m][n]);
        }
        __syncthreads();
    }

    // epilogue: dist = sqrt(max(x2 + m2 - 2*dot, 0) + eps)
    float m2v[8];
    #pragma unroll
    for (int n = 0; n < 8; n++) m2v[n] = g_m2[bn + tc + n];

    #pragma unroll
    for (int m = 0; m < 8; m++) {
        int i = bm + tr + m;
        float xi = g_x2[i];
        float* drow = g_dist + (size_t)i * M_ROWS + bn + tc;
        #pragma unroll
        for (int n0 = 0; n0 < 8; n0 += 4) {
            float4 o;
            float d;
            d = xi + m2v[n0 + 0] - 2.0f * acc[m][n0 + 0]; o.x = sqrtf(fmaxf(d, 0.0f) + EPSF);
            d = xi + m2v[n0 + 1] - 2.0f * acc[m][n0 + 1]; o.y = sqrtf(fmaxf(d, 0.0f) + EPSF);
            d = xi + m2v[n0 + 2] - 2.0f * acc[m][n0 + 2]; o.z = sqrtf(fmaxf(d, 0.0f) + EPSF);
            d = xi + m2v[n0 + 3] - 2.0f * acc[m][n0 + 3]; o.w = sqrtf(fmaxf(d, 0.0f) + EPSF);
            *(float4*)(drow + n0) = o;
        }
    }
}

// ---------------- top-K per row (1 block / row) ----------------
// Each thread keeps a sorted local top-10 over its strided slice; then 10
// rounds of block-wide lexicographic (dist, idx) argmin merge.
__global__ __launch_bounds__(256) void topk_kernel(float* __restrict__ out) {
    const int row = blockIdx.x;
    const float* dr = g_dist + (size_t)row * M_ROWS;
    float* knn_out = out + 2 * (size_t)N_ROWS * D_DIM + (size_t)row * K_TOP;

    float ld[K_TOP];
    int   li[K_TOP];
    #pragma unroll
    for (int k = 0; k < K_TOP; k++) { ld[k] = FLT_MAX; li[k] = 0x7fffffff; }

    for (int j = threadIdx.x; j < M_ROWS; j += 256) {
        float d = dr[j];
        if (d < ld[K_TOP - 1] || (d == ld[K_TOP - 1] && j < li[K_TOP - 1])) {
            int k = K_TOP - 1;
            while (k > 0 && (d < ld[k - 1] || (d == ld[k - 1] && j < li[k - 1]))) {
                ld[k] = ld[k - 1]; li[k] = li[k - 1]; k--;
            }
            ld[k] = d; li[k] = j;
        }
    }

    __shared__ float cd[256];
    __shared__ int   ci[256];

    int p = 0;
    float sum = 0.0f;
    for (int r = 0; r < K_TOP; r++) {
        cd[threadIdx.x] = (p < K_TOP) ? ld[p] : FLT_MAX;
        ci[threadIdx.x] = (p < K_TOP) ? li[p] : 0x7fffffff;
        __syncthreads();
        for (int s = 128; s > 0; s >>= 1) {
            if (threadIdx.x < s) {
                float d2 = cd[threadIdx.x + s]; int i2 = ci[threadIdx.x + s];
                float d1 = cd[threadIdx.x];     int i1 = ci[threadIdx.x];
                if (d2 < d1 || (d2 == d1 && i2 < i1)) { cd[threadIdx.x] = d2; ci[threadIdx.x] = i2; }
            }
            __syncthreads();
        }
        float win_d = cd[0];
        int   win_i = ci[0];
        __syncthreads();  // before next round overwrites cd/ci
        if (p < K_TOP && ld[p] == win_d && li[p] == win_i) p++;
        if (threadIdx.x == 0) {
            knn_out[r] = win_d;
            if (r == 0) g_idx0[row] = win_i;
        }
        sum += win_d;
    }

    if (threadIdx.x == 0) {
        float mean = sum * 0.1f;
        g_mean[row] = mean;
        atomicMin(&g_dmin_bits, __float_as_int(mean));  // positive floats: int order == float order
        atomicMax(&g_dmax_bits, __float_as_int(mean));
    }
}

// ---------------- final epilogue: influence + noise_std ----------------
__global__ __launch_bounds__(128) void final_kernel(const float* __restrict__ feat,
                                                    const float* __restrict__ mem,
                                                    const float* __restrict__ iscale,
                                                    const float* __restrict__ dscale,
                                                    float* __restrict__ out) {
    const int row = blockIdx.x;
    const int t = threadIdx.x;

    const float* knn = out + 2 * (size_t)N_ROWS * D_DIM;
    float norm = knn[(size_t)row * K_TOP] + EPSF;
    float inv = 1.0f / norm;
    int idx0 = g_idx0[row];

    float4 f  = *(const float4*)(feat + (size_t)row * D_DIM + t * 4);
    float4 nb = *(const float4*)(mem + (size_t)idx0 * D_DIM + t * 4);

    float v0 = fabsf((f.x - nb.x) * inv);
    float v1 = fabsf((f.y - nb.y) * inv);
    float v2 = fabsf((f.z - nb.z) * inv);
    float v3 = fabsf((f.w - nb.w) * inv);

    float mn = fminf(fminf(v0, v1), fminf(v2, v3));
    float mx = fmaxf(fmaxf(v0, v1), fmaxf(v2, v3));
    #pragma unroll
    for (int o = 16; o; o >>= 1) {
        mn = fminf(mn, __shfl_down_sync(0xffffffffu, mn, o));
        mx = fmaxf(mx, __shfl_down_sync(0xffffffffu, mx, o));
    }
    __shared__ float smn[4], smx[4];
    __shared__ float bmn, bmx;
    if ((t & 31) == 0) { smn[t >> 5] = mn; smx[t >> 5] = mx; }
    __syncthreads();
    if (t == 0) {
        bmn = fminf(fminf(smn[0], smn[1]), fminf(smn[2], smn[3]));
        bmx = fmaxf(fmaxf(smx[0], smx[1]), fmaxf(smx[2], smx[3]));
    }
    __syncthreads();
    float inf_min = bmn;
    float rinv = 1.0f / (bmx - inf_min + EPSF);

    float dmin = __int_as_float(g_dmin_bits);
    float dmax = __int_as_float(g_dmax_bits);
    float dn = (g_mean[row] - dmin) / (dmax - dmin + EPSF);

    float si = iscale[0], sd = dscale[0];
    float base = sd * dn - 0.5f;

    // influence
    *(float4*)(out + (size_t)row * D_DIM + t * 4) = make_float4(v0, v1, v2, v3);

    // noise_std = 0.01 + 0.49 * sigmoid(combined - 0.5)
    float4 ns;
    float c;
    c = si * ((v0 - inf_min) * rinv) + base; ns.x = 0.01f + 0.49f / (1.0f + expf(-c));
    c = si * ((v1 - inf_min) * rinv) + base; ns.y = 0.01f + 0.49f / (1.0f + expf(-c));
    c = si * ((v2 - inf_min) * rinv) + base; ns.z = 0.01f + 0.49f / (1.0f + expf(-c));
    c = si * ((v3 - inf_min) * rinv) + base; ns.w = 0.01f + 0.49f / (1.0f + expf(-c));
    *(float4*)(out + (size_t)N_ROWS * D_DIM + (size_t)row * D_DIM + t * 4) = ns;
}

// ---------------- launch ----------------
extern "C" void kernel_launch(void* const* d_in, const int* in_sizes, int n_in,
                              void* d_out, int out_size) {
    const float* feat = (const float*)d_in[0];
    const float* mem  = (const float*)d_in[1];
    const float* isc  = (const float*)d_in[2];
    const float* dsc  = (const float*)d_in[3];
    float* out = (float*)d_out;

    init_kernel<<<1, 1>>>();
    rowsumsq<<<N_ROWS, 128>>>(feat, 0);
    rowsumsq<<<M_ROWS, 128>>>(mem, 1);

    dim3 ggrid(M_ROWS / 128, N_ROWS / 128);  // (128, 64)
    gemm_dist<<<ggrid, 256>>>(feat, mem);

    topk_kernel<<<N_ROWS, 256>>>(out);
    final_kernel<<<N_ROWS, 128>>>(feat, mem, isc, dsc, out);
}

// round 2
// speedup vs baseline: 1.2604x; 1.2604x over previous
#include <cuda_runtime.h>
#include <math.h>
#include <float.h>

#define N_ROWS 8192
#define M_ROWS 16384
#define D_DIM  512
#define K_TOP  10
#define EPSF   1e-8f

// ---------------- device scratch (no allocations allowed) ----------------
__device__ float g_dist[(size_t)N_ROWS * (size_t)M_ROWS];  // 512 MB distance matrix
__device__ float g_x2[N_ROWS];
__device__ float g_m2[M_ROWS];
__device__ float g_mean[N_ROWS];
__device__ int   g_idx0[N_ROWS];
__device__ int   g_dmin_bits;
__device__ int   g_dmax_bits;

// ---------------- init (reset per launch; graph-replay safe) ----------------
__global__ void init_kernel() {
    g_dmin_bits = 0x7f7fffff;  // FLT_MAX
    g_dmax_bits = 0;           // all means are > 0
}

// ---------------- row sum-of-squares: 1 block (128 thr) per row of 512 ----------------
__global__ __launch_bounds__(128) void rowsumsq(const float* __restrict__ src, int which) {
    float* dst = which ? g_m2 : g_x2;
    int row = blockIdx.x;
    const float4* p = (const float4*)(src + (size_t)row * D_DIM);
    float4 v = p[threadIdx.x];
    float s = v.x * v.x + v.y * v.y + v.z * v.z + v.w * v.w;
    #pragma unroll
    for (int o = 16; o; o >>= 1) s += __shfl_down_sync(0xffffffffu, s, o);
    __shared__ float ws[4];
    if ((threadIdx.x & 31) == 0) ws[threadIdx.x >> 5] = s;
    __syncthreads();
    if (threadIdx.x == 0) dst[row] = ws[0] + ws[1] + ws[2] + ws[3];
}

// ---------------- SGEMM -> euclidean distance matrix ----------------
// C tile 128x128, K tile 16, 256 threads, 8x8 per-thread register tile.
// Double-buffered SMEM with register-staged global prefetch: 1 sync per k-tile.
__global__ __launch_bounds__(256) void gemm_dist(const float* __restrict__ A,   // features [N,D]
                                                 const float* __restrict__ B) { // memory   [M,D]
    __shared__ float As[2][16][128];
    __shared__ float Bs[2][16][128];

    const int bm = blockIdx.y * 128;   // feature rows
    const int bn = blockIdx.x * 128;   // memory rows
    const int tid = threadIdx.x;
    const int tr = (tid >> 4) << 3;    // 0..120 step 8 (rows)
    const int tc = (tid & 15) << 3;    // 0..120 step 8 (cols)

    // per-thread gmem staging coordinates (2 float4 per operand per tile)
    const int r0 = (tid) >> 2;                 // 0..63
    const int r1 = (tid + 256) >> 2;           // 64..127
    const int c4 = (tid & 3) << 2;             // 0,4,8,12

    float acc[8][8];
    #pragma unroll
    for (int m = 0; m < 8; m++)
        #pragma unroll
        for (int n = 0; n < 8; n++) acc[m][n] = 0.0f;

    const float* Ap0 = A + (size_t)(bm + r0) * D_DIM + c4;
    const float* Ap1 = A + (size_t)(bm + r1) * D_DIM + c4;
    const float* Bp0 = B + (size_t)(bn + r0) * D_DIM + c4;
    const float* Bp1 = B + (size_t)(bn + r1) * D_DIM + c4;

    // preload tile 0 into buffer 0
    {
        float4 va0 = *(const float4*)(Ap0);
        float4 va1 = *(const float4*)(Ap1);
        float4 vb0 = *(const float4*)(Bp0);
        float4 vb1 = *(const float4*)(Bp1);
        As[0][c4 + 0][r0] = va0.x; As[0][c4 + 1][r0] = va0.y; As[0][c4 + 2][r0] = va0.z; As[0][c4 + 3][r0] = va0.w;
        As[0][c4 + 0][r1] = va1.x; As[0][c4 + 1][r1] = va1.y; As[0][c4 + 2][r1] = va1.z; As[0][c4 + 3][r1] = va1.w;
        Bs[0][c4 + 0][r0] = vb0.x; Bs[0][c4 + 1][r0] = vb0.y; Bs[0][c4 + 2][r0] = vb0.z; Bs[0][c4 + 3][r0] = vb0.w;
        Bs[0][c4 + 0][r1] = vb1.x; Bs[0][c4 + 1][r1] = vb1.y; Bs[0][c4 + 2][r1] = vb1.z; Bs[0][c4 + 3][r1] = vb1.w;
    }
    __syncthreads();

    #pragma unroll 1
    for (int t = 0; t < 32; t++) {
        const int cur = t & 1;
        const int nxt = cur ^ 1;

        // prefetch next k-tile from gmem into registers (overlaps with compute)
        float4 va0, va1, vb0, vb1;
        const bool more = (t < 31);
        if (more) {
            int k0 = (t + 1) * 16;
            va0 = *(const float4*)(Ap0 + k0);
            va1 = *(const float4*)(Ap1 + k0);
            vb0 = *(const float4*)(Bp0 + k0);
            vb1 = *(const float4*)(Bp1 + k0);
        }

        // compute on current buffer
        #pragma unroll
        for (int k = 0; k < 16; k++) {
            float a[8], b[8];
            #pragma unroll
            for (int m = 0; m < 8; m++) a[m] = As[cur][k][tr + m];
            #pragma unroll
            for (int n = 0; n < 8; n++) b[n] = Bs[cur][k][tc + n];
            #pragma unroll
            for (int m = 0; m < 8; m++)
                #pragma unroll
                for (int n = 0; n < 8; n++) acc[m][n] = fmaf(a[m], b[n], acc[m][n]);
        }

        // stage next tile into the other buffer
        if (more) {
            As[nxt][c4 + 0][r0] = va0.x; As[nxt][c4 + 1][r0] = va0.y; As[nxt][c4 + 2][r0] = va0.z; As[nxt][c4 + 3][r0] = va0.w;
            As[nxt][c4 + 0][r1] = va1.x; As[nxt][c4 + 1][r1] = va1.y; As[nxt][c4 + 2][r1] = va1.z; As[nxt][c4 + 3][r1] = va1.w;
            Bs[nxt][c4 + 0][r0] = vb0.x; Bs[nxt][c4 + 1][r0] = vb0.y; Bs[nxt][c4 + 2][r0] = vb0.z; Bs[nxt][c4 + 3][r0] = vb0.w;
            Bs[nxt][c4 + 0][r1] = vb1.x; Bs[nxt][c4 + 1][r1] = vb1.y; Bs[nxt][c4 + 2][r1] = vb1.z; Bs[nxt][c4 + 3][r1] = vb1.w;
        }
        __syncthreads();
    }

    // epilogue: dist = sqrt(max(x2 + m2 - 2*dot, 0) + eps)
    float m2v[8];
    #pragma unroll
    for (int n = 0; n < 8; n++) m2v[n] = g_m2[bn + tc + n];

    #pragma unroll
    for (int m = 0; m < 8; m++) {
        int i = bm + tr + m;
        float xi = g_x2[i];
        float* drow = g_dist + (size_t)i * M_ROWS + bn + tc;
        #pragma unroll
        for (int n0 = 0; n0 < 8; n0 += 4) {
            float4 o;
            float d;
            d = xi + m2v[n0 + 0] - 2.0f * acc[m][n0 + 0]; o.x = sqrtf(fmaxf(d, 0.0f) + EPSF);
            d = xi + m2v[n0 + 1] - 2.0f * acc[m][n0 + 1]; o.y = sqrtf(fmaxf(d, 0.0f) + EPSF);
            d = xi + m2v[n0 + 2] - 2.0f * acc[m][n0 + 2]; o.z = sqrtf(fmaxf(d, 0.0f) + EPSF);
            d = xi + m2v[n0 + 3] - 2.0f * acc[m][n0 + 3]; o.w = sqrtf(fmaxf(d, 0.0f) + EPSF);
            *(float4*)(drow + n0) = o;
        }
    }
}

// ---------------- top-K per row (1 block / row) ----------------
// Register-resident sorted top-10 per thread (constant-index unrolled insert
// network -> no local memory), then 10 rounds of block-wide lexicographic
// (dist, idx) argmin merge with constant-index shift-down.
__global__ __launch_bounds__(256) void topk_kernel(float* __restrict__ out) {
    const int row = blockIdx.x;
    const float4* dr4 = (const float4*)(g_dist + (size_t)row * M_ROWS);
    float* knn_out = out + 2 * (size_t)N_ROWS * D_DIM + (size_t)row * K_TOP;

    float ld[K_TOP];
    int   li[K_TOP];
    #pragma unroll
    for (int k = 0; k < K_TOP; k++) { ld[k] = FLT_MAX; li[k] = 0x7fffffff; }

    // scan: each thread reads 16 float4 (64 elements), coalesced
    #pragma unroll 1
    for (int it = 0; it < M_ROWS / (256 * 4); it++) {
        int base = it * 1024 + threadIdx.x * 4;
        float4 v = dr4[it * 256 + threadIdx.x];
        float dv[4] = {v.x, v.y, v.z, v.w};
        #pragma unroll
        for (int e = 0; e < 4; e++) {
            float x = dv[e];
            int   xi = base + e;
            if (x < ld[K_TOP - 1] || (x == ld[K_TOP - 1] && xi < li[K_TOP - 1])) {
                // unrolled compare-and-swap insertion (constant indices only)
                #pragma unroll
                for (int k = 0; k < K_TOP; k++) {
                    bool lt = (x < ld[k]) || (x == ld[k] && xi < li[k]);
                    float td = lt ? ld[k] : x;  int ti = lt ? li[k] : xi;
                    ld[k] = lt ? x : ld[k];     li[k] = lt ? xi : li[k];
                    x = td; xi = ti;
                }
            }
        }
    }

    __shared__ float cd[256];
    __shared__ int   ci[256];

    float sum = 0.0f;
    #pragma unroll 1
    for (int r = 0; r < K_TOP; r++) {
        cd[threadIdx.x] = ld[0];
        ci[threadIdx.x] = li[0];
        __syncthreads();
        for (int s = 128; s > 0; s >>= 1) {
            if (threadIdx.x < s) {
                float d2 = cd[threadIdx.x + s]; int i2 = ci[threadIdx.x + s];
                float d1 = cd[threadIdx.x];     int i1 = ci[threadIdx.x];
                if (d2 < d1 || (d2 == d1 && i2 < i1)) { cd[threadIdx.x] = d2; ci[threadIdx.x] = i2; }
            }
            __syncthreads();
        }
        float win_d = cd[0];
        int   win_i = ci[0];
        __syncthreads();  // before next round overwrites cd/ci

        // if my head was consumed, shift down (constant indices)
        if (ld[0] == win_d && li[0] == win_i) {
            #pragma unroll
            for (int k = 0; k < K_TOP - 1; k++) { ld[k] = ld[k + 1]; li[k] = li[k + 1]; }
            ld[K_TOP - 1] = FLT_MAX; li[K_TOP - 1] = 0x7fffffff;
        }

        if (threadIdx.x == 0) {
            knn_out[r] = win_d;
            if (r == 0) g_idx0[row] = win_i;
        }
        sum += win_d;
    }

    if (threadIdx.x == 0) {
        float mean = sum * 0.1f;
        g_mean[row] = mean;
        atomicMin(&g_dmin_bits, __float_as_int(mean));  // positive floats: int order == float order
        atomicMax(&g_dmax_bits, __float_as_int(mean));
    }
}

// ---------------- final epilogue: influence + noise_std ----------------
__global__ __launch_bounds__(128) void final_kernel(const float* __restrict__ feat,
                                                    const float* __restrict__ mem,
                                                    const float* __restrict__ iscale,
                                                    const float* __restrict__ dscale,
                                                    float* __restrict__ out) {
    const int row = blockIdx.x;
    const int t = threadIdx.x;

    const float* knn = out + 2 * (size_t)N_ROWS * D_DIM;
    float norm = knn[(size_t)row * K_TOP] + EPSF;
    float inv = 1.0f / norm;
    int idx0 = g_idx0[row];

    float4 f  = *(const float4*)(feat + (size_t)row * D_DIM + t * 4);
    float4 nb = *(const float4*)(mem + (size_t)idx0 * D_DIM + t * 4);

    float v0 = fabsf((f.x - nb.x) * inv);
    float v1 = fabsf((f.y - nb.y) * inv);
    float v2 = fabsf((f.z - nb.z) * inv);
    float v3 = fabsf((f.w - nb.w) * inv);

    float mn = fminf(fminf(v0, v1), fminf(v2, v3));
    float mx = fmaxf(fmaxf(v0, v1), fmaxf(v2, v3));
    #pragma unroll
    for (int o = 16; o; o >>= 1) {
        mn = fminf(mn, __shfl_down_sync(0xffffffffu, mn, o));
        mx = fmaxf(mx, __shfl_down_sync(0xffffffffu, mx, o));
    }
    __shared__ float smn[4], smx[4];
    __shared__ float bmn, bmx;
    if ((t & 31) == 0) { smn[t >> 5] = mn; smx[t >> 5] = mx; }
    __syncthreads();
    if (t == 0) {
        bmn = fminf(fminf(smn[0], smn[1]), fminf(smn[2], smn[3]));
        bmx = fmaxf(fmaxf(smx[0], smx[1]), fmaxf(smx[2], smx[3]));
    }
    __syncthreads();
    float inf_min = bmn;
    float rinv = 1.0f / (bmx - inf_min + EPSF);

    float dmin = __int_as_float(g_dmin_bits);
    float dmax = __int_as_float(g_dmax_bits);
    float dn = (g_mean[row] - dmin) / (dmax - dmin + EPSF);

    float si = iscale[0], sd = dscale[0];
    float base = sd * dn - 0.5f;

    // influence
    *(float4*)(out + (size_t)row * D_DIM + t * 4) = make_float4(v0, v1, v2, v3);

    // noise_std = 0.01 + 0.49 * sigmoid(combined - 0.5)
    float4 ns;
    float c;
    c = si * ((v0 - inf_min) * rinv) + base; ns.x = 0.01f + 0.49f / (1.0f + expf(-c));
    c = si * ((v1 - inf_min) * rinv) + base; ns.y = 0.01f + 0.49f / (1.0f + expf(-c));
    c = si * ((v2 - inf_min) * rinv) + base; ns.z = 0.01f + 0.49f / (1.0f + expf(-c));
    c = si * ((v3 - inf_min) * rinv) + base; ns.w = 0.01f + 0.49f / (1.0f + expf(-c));
    *(float4*)(out + (size_t)N_ROWS * D_DIM + (size_t)row * D_DIM + t * 4) = ns;
}

// ---------------- launch ----------------
extern "C" void kernel_launch(void* const* d_in, const int* in_sizes, int n_in,
                              void* d_out, int out_size) {
    const float* feat = (const float*)d_in[0];
    const float* mem  = (const float*)d_in[1];
    const float* isc  = (const float*)d_in[2];
    const float* dsc  = (const float*)d_in[3];
    float* out = (float*)d_out;

    init_kernel<<<1, 1>>>();
    rowsumsq<<<N_ROWS, 128>>>(feat, 0);
    rowsumsq<<<M_ROWS, 128>>>(mem, 1);

    dim3 ggrid(M_ROWS / 128, N_ROWS / 128);  // (128, 64)
    gemm_dist<<<ggrid, 256>>>(feat, mem);

    topk_kernel<<<N_ROWS, 256>>>(out);
    final_kernel<<<N_ROWS, 128>>>(feat, mem, isc, dsc, out);
}

// round 4
// speedup vs baseline: 2.4009x; 1.9049x over previous
#include <cuda_runtime.h>
#include <cuda_bf16.h>
#include <math.h>
#include <float.h>
#include <stdint.h>

#define N_ROWS 8192
#define M_ROWS 16384
#define D_DIM  512
#define K_TOP  10
#define K_CAND 16
#define EPSF   1e-8f

// ================= helpers =================
__device__ __forceinline__ uint32_t smem_u32(const void* p) {
    uint32_t a;
    asm("{ .reg .u64 t; cvta.to.shared.u64 t, %1; cvt.u32.u64 %0, t; }" : "=r"(a) : "l"(p));
    return a;
}
#define CP_ASYNC16(dst, src) asm volatile("cp.async.cg.shared.global [%0], [%1], 16;" :: "r"(dst), "l"(src) : "memory")
#define CP_COMMIT()          asm volatile("cp.async.commit_group;" ::: "memory")
#define CP_WAIT(n)           asm volatile("cp.async.wait_group %0;" :: "n"(n) : "memory")

#define LDSM_X4(r0, r1, r2, r3, a) \
    asm volatile("ldmatrix.sync.aligned.m8n8.x4.shared.b16 {%0,%1,%2,%3}, [%4];" \
        : "=r"(r0), "=r"(r1), "=r"(r2), "=r"(r3) : "r"(a))

#define MMA16816(c0, c1, c2, c3, a0, a1, a2, a3, b0, b1) \
    asm volatile("mma.sync.aligned.m16n8k16.row.col.f32.bf16.bf16.f32 " \
        "{%0,%1,%2,%3}, {%4,%5,%6,%7}, {%8,%9}, {%0,%1,%2,%3};" \
        : "+f"(c0), "+f"(c1), "+f"(c2), "+f"(c3) \
        : "r"(a0), "r"(a1), "r"(a2), "r"(a3), "r"(b0), "r"(b1))

// ================= device scratch =================
__device__ float g_dist[(size_t)N_ROWS * (size_t)M_ROWS];  // 512 MB approx distance matrix
__device__ __nv_bfloat16 g_abf[(size_t)N_ROWS * D_DIM];
__device__ __nv_bfloat16 g_bbf[(size_t)M_ROWS * D_DIM];
__device__ float g_x2[N_ROWS];
__device__ float g_m2[M_ROWS];
__device__ float g_mean[N_ROWS];
__device__ int   g_idx0[N_ROWS];
__device__ int   g_cand[(size_t)N_ROWS * K_CAND];
__device__ int   g_dmin_bits;
__device__ int   g_dmax_bits;

// ================= init =================
__global__ void init_kernel() {
    g_dmin_bits = 0x7f7fffff;
    g_dmax_bits = 0;
}

// ================= fp32 -> bf16 =================
__global__ __launch_bounds__(256) void prep_bf16(const float* __restrict__ A,
                                                 const float* __restrict__ B) {
    int i = blockIdx.x * 256 + threadIdx.x;
    const int NA = N_ROWS * D_DIM;
    const int NB = M_ROWS * D_DIM;
    if (i < NA) g_abf[i] = __float2bfloat16(A[i]);
    if (i < NB) g_bbf[i] = __float2bfloat16(B[i]);
}

// ================= row sum-of-squares =================
__global__ __launch_bounds__(128) void rowsumsq(const float* __restrict__ src, int which) {
    float* dst = which ? g_m2 : g_x2;
    int row = blockIdx.x;
    const float4* p = (const float4*)(src + (size_t)row * D_DIM);
    float4 v = p[threadIdx.x];
    float s = v.x * v.x + v.y * v.y + v.z * v.z + v.w * v.w;
    #pragma unroll
    for (int o = 16; o; o >>= 1) s += __shfl_down_sync(0xffffffffu, s, o);
    __shared__ float ws[4];
    if ((threadIdx.x & 31) == 0) ws[threadIdx.x >> 5] = s;
    __syncthreads();
    if (threadIdx.x == 0) dst[row] = ws[0] + ws[1] + ws[2] + ws[3];
}

// ================= bf16 HMMA GEMM -> distance matrix =================
// 128x128 tile, BK=32, 256 threads = 8 warps (2m x 4n), warp tile 64x32.
// smem rows padded to 80B (5 x 16B -> conflict-free ldmatrix).
#define ROWB   80            // bytes per smem row (32 bf16 padded to 40)
#define STAGEB (128 * ROWB)  // 10240 B per matrix per stage

__global__ __launch_bounds__(256, 2) void gemm_dist_mma() {
    __shared__ __align__(128) uint8_t As[2 * STAGEB];
    __shared__ __align__(128) uint8_t Bs[2 * STAGEB];

    const int tid  = threadIdx.x;
    const int lane = tid & 31;
    const int wid  = tid >> 5;
    const int wm   = wid >> 2;          // 0..1
    const int wn   = wid & 3;           // 0..3
    const int bm   = blockIdx.y * 128;  // feature rows
    const int bn   = blockIdx.x * 128;  // memory rows

    const uint32_t sbA = smem_u32(As);
    const uint32_t sbB = smem_u32(Bs);

    // cp.async staging coords: 2 chunks per thread per matrix
    const int r0 = tid >> 2;            // 0..63
    const int r1 = (tid + 256) >> 2;    // 64..127
    const int kc = (tid & 3);           // 16B chunk in 64B row
    const __nv_bfloat16* gA0 = g_abf + (size_t)(bm + r0) * D_DIM + kc * 8;
    const __nv_bfloat16* gA1 = g_abf + (size_t)(bm + r1) * D_DIM + kc * 8;
    const __nv_bfloat16* gB0 = g_bbf + (size_t)(bn + r0) * D_DIM + kc * 8;
    const __nv_bfloat16* gB1 = g_bbf + (size_t)(bn + r1) * D_DIM + kc * 8;
    const uint32_t dA0 = sbA + r0 * ROWB + kc * 16;
    const uint32_t dA1 = sbA + r1 * ROWB + kc * 16;
    const uint32_t dB0 = sbB + r0 * ROWB + kc * 16;
    const uint32_t dB1 = sbB + r1 * ROWB + kc * 16;

    // ldmatrix per-thread offsets
    const int lrow = (lane & 7) + ((lane >> 3) & 1) * 8;  // 0..15
    const int lcol = (lane >> 4) * 8;                     // 0 or 8
    uint32_t aAddr[2][4], bAddr[2][2];
    #pragma unroll
    for (int b = 0; b < 2; b++) {
        #pragma unroll
        for (int mf = 0; mf < 4; mf++)
            aAddr[b][mf] = sbA + b * STAGEB + (wm * 64 + mf * 16 + lrow) * ROWB + lcol * 2;
        #pragma unroll
        for (int np = 0; np < 2; np++)
            bAddr[b][np] = sbB + b * STAGEB + (wn * 32 + np * 16 + lrow) * ROWB + lcol * 2;
    }

    float acc[4][4][4];
    #pragma unroll
    for (int mf = 0; mf < 4; mf++)
        #pragma unroll
        for (int nf = 0; nf < 4; nf++)
            #pragma unroll
            for (int e = 0; e < 4; e++) acc[mf][nf][e] = 0.0f;

    // preload stage 0 -> buf 0
    CP_ASYNC16(dA0, gA0); CP_ASYNC16(dA1, gA1);
    CP_ASYNC16(dB0, gB0); CP_ASYNC16(dB1, gB1);
    CP_COMMIT();

    #pragma unroll 1
    for (int kt = 0; kt < 16; kt++) {
        const int b = kt & 1;
        if (kt < 15) {
            const int off = (kt + 1) * 32;           // bf16 elems
            const uint32_t so = (b ^ 1) * STAGEB;
            CP_ASYNC16(dA0 + so, gA0 + off); CP_ASYNC16(dA1 + so, gA1 + off);
            CP_ASYNC16(dB0 + so, gB0 + off); CP_ASYNC16(dB1 + so, gB1 + off);
            CP_COMMIT();
            CP_WAIT(1);
        } else {
            CP_WAIT(0);
        }
        __syncthreads();

        #pragma unroll
        for (int ks = 0; ks < 2; ks++) {
            const int ko = ks * 32;  // 16 bf16 = 32 B
            uint32_t af[4][4], bf[2][4];
            #pragma unroll
            for (int mf = 0; mf < 4; mf++)
                LDSM_X4(af[mf][0], af[mf][1], af[mf][2], af[mf][3], aAddr[b][mf] + ko);
            #pragma unroll
            for (int np = 0; np < 2; np++)
                LDSM_X4(bf[np][0], bf[np][1], bf[np][2], bf[np][3], bAddr[b][np] + ko);

            #pragma unroll
            for (int mf = 0; mf < 4; mf++) {
                #pragma unroll
                for (int nf = 0; nf < 4; nf++) {
                    const int np = nf >> 1, o = nf & 1;
                    MMA16816(acc[mf][nf][0], acc[mf][nf][1], acc[mf][nf][2], acc[mf][nf][3],
                             af[mf][0], af[mf][1], af[mf][2], af[mf][3],
                             bf[np][0 + o], bf[np][2 + o]);
                }
            }
        }
        __syncthreads();
    }

    // epilogue: dist = sqrt(max(x2 + m2 - 2*dot, 0) + eps)
    const int q = lane >> 2, p = lane & 3;
    #pragma unroll
    for (int mf = 0; mf < 4; mf++) {
        const int rg0 = bm + wm * 64 + mf * 16 + q;
        const float xi0 = g_x2[rg0];
        const float xi1 = g_x2[rg0 + 8];
        float* dr0 = g_dist + (size_t)rg0 * M_ROWS;
        float* dr1 = g_dist + (size_t)(rg0 + 8) * M_ROWS;
        #pragma unroll
        for (int nf = 0; nf < 4; nf++) {
            const int cg = bn + wn * 32 + nf * 8 + p * 2;
            const float m20 = g_m2[cg], m21 = g_m2[cg + 1];
            float2 o;
            float d;
            d = xi0 + m20 - 2.0f * acc[mf][nf][0]; o.x = sqrtf(fmaxf(d, 0.0f) + EPSF);
            d = xi0 + m21 - 2.0f * acc[mf][nf][1]; o.y = sqrtf(fmaxf(d, 0.0f) + EPSF);
            *(float2*)(dr0 + cg) = o;
            d = xi1 + m20 - 2.0f * acc[mf][nf][2]; o.x = sqrtf(fmaxf(d, 0.0f) + EPSF);
            d = xi1 + m21 - 2.0f * acc[mf][nf][3]; o.y = sqrtf(fmaxf(d, 0.0f) + EPSF);
            *(float2*)(dr1 + cg) = o;
        }
    }
}

// ================= top-16 candidates per row =================
__global__ __launch_bounds__(256) void topk_kernel() {
    const int row = blockIdx.x;
    const float4* dr4 = (const float4*)(g_dist + (size_t)row * M_ROWS);

    float ld[K_CAND];
    int   li[K_CAND];
    #pragma unroll
    for (int k = 0; k < K_CAND; k++) { ld[k] = FLT_MAX; li[k] = 0x7fffffff; }

    #pragma unroll 1
    for (int it = 0; it < M_ROWS / (256 * 4); it++) {
        int base = it * 1024 + threadIdx.x * 4;
        float4 v = dr4[it * 256 + threadIdx.x];
        float dv[4] = {v.x, v.y, v.z, v.w};
        #pragma unroll
        for (int e = 0; e < 4; e++) {
            float x = dv[e];
            int   xi = base + e;
            if (x < ld[K_CAND - 1] || (x == ld[K_CAND - 1] && xi < li[K_CAND - 1])) {
                #pragma unroll
                for (int k = 0; k < K_CAND; k++) {
                    bool lt = (x < ld[k]) || (x == ld[k] && xi < li[k]);
                    float td = lt ? ld[k] : x;  int ti = lt ? li[k] : xi;
                    ld[k] = lt ? x : ld[k];     li[k] = lt ? xi : li[k];
                    x = td; xi = ti;
                }
            }
        }
    }

    __shared__ float cd[256];
    __shared__ int   ci[256];

    #pragma unroll 1
    for (int r = 0; r < K_CAND; r++) {
        cd[threadIdx.x] = ld[0];
        ci[threadIdx.x] = li[0];
        __syncthreads();
        for (int s = 128; s > 0; s >>= 1) {
            if (threadIdx.x < s) {
                float d2 = cd[threadIdx.x + s]; int i2 = ci[threadIdx.x + s];
                float d1 = cd[threadIdx.x];     int i1 = ci[threadIdx.x];
                if (d2 < d1 || (d2 == d1 && i2 < i1)) { cd[threadIdx.x] = d2; ci[threadIdx.x] = i2; }
            }
            __syncthreads();
        }
        float win_d = cd[0];
        int   win_i = ci[0];
        __syncthreads();

        if (ld[0] == win_d && li[0] == win_i) {
            #pragma unroll
            for (int k = 0; k < K_CAND - 1; k++) { ld[k] = ld[k + 1]; li[k] = li[k + 1]; }
            ld[K_CAND - 1] = FLT_MAX; li[K_CAND - 1] = 0x7fffffff;
        }
        if (threadIdx.x == 0) g_cand[(size_t)row * K_CAND + r] = win_i;
    }
}

// ================= exact rerank of 16 candidates =================
__global__ __launch_bounds__(512) void rerank_kernel(const float* __restrict__ feat,
                                                     const float* __restrict__ mem,
                                                     float* __restrict__ out) {
    const int row = blockIdx.x;
    const int wid = threadIdx.x >> 5;
    const int lid = threadIdx.x & 31;

    __shared__ float sd[K_CAND];
    __shared__ int   si[K_CAND];

    int cand = g_cand[(size_t)row * K_CAND + wid];
    const float4* f4 = (const float4*)(feat + (size_t)row * D_DIM);
    const float4* m4 = (const float4*)(mem + (size_t)cand * D_DIM);
    float acc = 0.0f;
    #pragma unroll
    for (int i = 0; i < 4; i++) {
        float4 a = f4[lid + i * 32];
        float4 b = m4[lid + i * 32];
        acc += a.x * b.x + a.y * b.y + a.z * b.z + a.w * b.w;
    }
    #pragma unroll
    for (int o = 16; o; o >>= 1) acc += __shfl_down_sync(0xffffffffu, acc, o);
    if (lid == 0) {
        float d2 = g_x2[row] + g_m2[cand] - 2.0f * acc;
        sd[wid] = sqrtf(fmaxf(d2, 0.0f) + EPSF);
        si[wid] = cand;
    }
    __syncthreads();

    if (threadIdx.x == 0) {
        for (int i = 1; i < K_CAND; i++) {
            float d = sd[i]; int ix = si[i];
            int j = i - 1;
            while (j >= 0 && (sd[j] > d || (sd[j] == d && si[j] > ix))) {
                sd[j + 1] = sd[j]; si[j + 1] = si[j]; j--;
            }
            sd[j + 1] = d; si[j + 1] = ix;
        }
        float* knn_out = out + 2 * (size_t)N_ROWS * D_DIM + (size_t)row * K_TOP;
        float sum = 0.0f;
        #pragma unroll
        for (int k = 0; k < K_TOP; k++) { knn_out[k] = sd[k]; sum += sd[k]; }
        g_idx0[row] = si[0];
        float mean = sum * 0.1f;
        g_mean[row] = mean;
        atomicMin(&g_dmin_bits, __float_as_int(mean));
        atomicMax(&g_dmax_bits, __float_as_int(mean));
    }
}

// ================= final epilogue =================
__global__ __launch_bounds__(128) void final_kernel(const float* __restrict__ feat,
                                                    const float* __restrict__ mem,
                                                    const float* __restrict__ iscale,
                                                    const float* __restrict__ dscale,
                                                    float* __restrict__ out) {
    const int row = blockIdx.x;
    const int t = threadIdx.x;

    const float* knn = out + 2 * (size_t)N_ROWS * D_DIM;
    float norm = knn[(size_t)row * K_TOP] + EPSF;
    float inv = 1.0f / norm;
    int idx0 = g_idx0[row];

    float4 f  = *(const float4*)(feat + (size_t)row * D_DIM + t * 4);
    float4 nb = *(const float4*)(mem + (size_t)idx0 * D_DIM + t * 4);

    float v0 = fabsf((f.x - nb.x) * inv);
    float v1 = fabsf((f.y - nb.y) * inv);
    float v2 = fabsf((f.z - nb.z) * inv);
    float v3 = fabsf((f.w - nb.w) * inv);

    float mn = fminf(fminf(v0, v1), fminf(v2, v3));
    float mx = fmaxf(fmaxf(v0, v1), fmaxf(v2, v3));
    #pragma unroll
    for (int o = 16; o; o >>= 1) {
        mn = fminf(mn, __shfl_down_sync(0xffffffffu, mn, o));
        mx = fmaxf(mx, __shfl_down_sync(0xffffffffu, mx, o));
    }
    __shared__ float smn[4], smx[4];
    __shared__ float bmn, bmx;
    if ((t & 31) == 0) { smn[t >> 5] = mn; smx[t >> 5] = mx; }
    __syncthreads();
    if (t == 0) {
        bmn = fminf(fminf(smn[0], smn[1]), fminf(smn[2], smn[3]));
        bmx = fmaxf(fmaxf(smx[0], smx[1]), fmaxf(smx[2], smx[3]));
    }
    __syncthreads();
    float inf_min = bmn;
    float rinv = 1.0f / (bmx - inf_min + EPSF);

    float dmin = __int_as_float(g_dmin_bits);
    float dmax = __int_as_float(g_dmax_bits);
    float dn = (g_mean[row] - dmin) / (dmax - dmin + EPSF);

    float si = iscale[0], sd = dscale[0];
    float base = sd * dn - 0.5f;

    *(float4*)(out + (size_t)row * D_DIM + t * 4) = make_float4(v0, v1, v2, v3);

    float4 ns;
    float c;
    c = si * ((v0 - inf_min) * rinv) + base; ns.x = 0.01f + 0.49f / (1.0f + expf(-c));
    c = si * ((v1 - inf_min) * rinv) + base; ns.y = 0.01f + 0.49f / (1.0f + expf(-c));
    c = si * ((v2 - inf_min) * rinv) + base; ns.z = 0.01f + 0.49f / (1.0f + expf(-c));
    c = si * ((v3 - inf_min) * rinv) + base; ns.w = 0.01f + 0.49f / (1.0f + expf(-c));
    *(float4*)(out + (size_t)N_ROWS * D_DIM + (size_t)row * D_DIM + t * 4) = ns;
}

// ================= launch =================
extern "C" void kernel_launch(void* const* d_in, const int* in_sizes, int n_in,
                              void* d_out, int out_size) {
    const float* feat = (const float*)d_in[0];
    const float* mem  = (const float*)d_in[1];
    const float* isc  = (const float*)d_in[2];
    const float* dsc  = (const float*)d_in[3];
    float* out = (float*)d_out;

    init_kernel<<<1, 1>>>();
    prep_bf16<<<(M_ROWS * D_DIM + 255) / 256, 256>>>(feat, mem);
    rowsumsq<<<N_ROWS, 128>>>(feat, 0);
    rowsumsq<<<M_ROWS, 128>>>(mem, 1);

    dim3 ggrid(M_ROWS / 128, N_ROWS / 128);  // (128, 64)
    gemm_dist_mma<<<ggrid, 256>>>();

    topk_kernel<<<N_ROWS, 256>>>();
    rerank_kernel<<<N_ROWS, 512>>>(feat, mem, out);
    final_kernel<<<N_ROWS, 128>>>(feat, mem, isc, dsc, out);
}

// round 5
// speedup vs baseline: 3.4177x; 1.4235x over previous
#include <cuda_runtime.h>
#include <cuda_bf16.h>
#include <math.h>
#include <float.h>
#include <stdint.h>

#define N_ROWS 8192
#define M_ROWS 16384
#define D_DIM  512
#define K_TOP  10
#define K_CAND 16
#define EPSF   1e-8f

// ================= helpers =================
__device__ __forceinline__ uint32_t smem_u32(const void* p) {
    uint32_t a;
    asm("{ .reg .u64 t; cvta.to.shared.u64 t, %1; cvt.u32.u64 %0, t; }" : "=r"(a) : "l"(p));
    return a;
}
#define CP_ASYNC16(dst, src) asm volatile("cp.async.cg.shared.global [%0], [%1], 16;" :: "r"(dst), "l"(src) : "memory")
#define CP_COMMIT()          asm volatile("cp.async.commit_group;" ::: "memory")
#define CP_WAIT(n)           asm volatile("cp.async.wait_group %0;" :: "n"(n) : "memory")

#define LDSM_X4(r0, r1, r2, r3, a) \
    asm volatile("ldmatrix.sync.aligned.m8n8.x4.shared.b16 {%0,%1,%2,%3}, [%4];" \
        : "=r"(r0), "=r"(r1), "=r"(r2), "=r"(r3) : "r"(a))

#define MMA16816(c0, c1, c2, c3, a0, a1, a2, a3, b0, b1) \
    asm volatile("mma.sync.aligned.m16n8k16.row.col.f32.bf16.bf16.f32 " \
        "{%0,%1,%2,%3}, {%4,%5,%6,%7}, {%8,%9}, {%0,%1,%2,%3};" \
        : "+f"(c0), "+f"(c1), "+f"(c2), "+f"(c3) \
        : "r"(a0), "r"(a1), "r"(a2), "r"(a3), "r"(b0), "r"(b1))

// ================= device scratch =================
__device__ __nv_bfloat16 g_score[(size_t)N_ROWS * (size_t)M_ROWS];  // 256 MB bf16 score matrix
__device__ __nv_bfloat16 g_abf[(size_t)N_ROWS * D_DIM];
__device__ __nv_bfloat16 g_bbf[(size_t)M_ROWS * D_DIM];
__device__ float g_x2[N_ROWS];
__device__ float g_m2[M_ROWS];
__device__ float g_mean[N_ROWS];
__device__ int   g_idx0[N_ROWS];
__device__ int   g_cand[(size_t)N_ROWS * K_CAND];
__device__ int   g_dmin_bits;
__device__ int   g_dmax_bits;

// ================= init =================
__global__ void init_kernel() {
    g_dmin_bits = 0x7f7fffff;
    g_dmax_bits = 0;
}

// ================= fp32 -> bf16 =================
__global__ __launch_bounds__(256) void prep_bf16(const float* __restrict__ A,
                                                 const float* __restrict__ B) {
    int i = blockIdx.x * 256 + threadIdx.x;
    const int NA = N_ROWS * D_DIM;
    const int NB = M_ROWS * D_DIM;
    if (i < NA) g_abf[i] = __float2bfloat16(A[i]);
    if (i < NB) g_bbf[i] = __float2bfloat16(B[i]);
}

// ================= row sum-of-squares =================
__global__ __launch_bounds__(128) void rowsumsq(const float* __restrict__ src, int which) {
    float* dst = which ? g_m2 : g_x2;
    int row = blockIdx.x;
    const float4* p = (const float4*)(src + (size_t)row * D_DIM);
    float4 v = p[threadIdx.x];
    float s = v.x * v.x + v.y * v.y + v.z * v.z + v.w * v.w;
    #pragma unroll
    for (int o = 16; o; o >>= 1) s += __shfl_down_sync(0xffffffffu, s, o);
    __shared__ float ws[4];
    if ((threadIdx.x & 31) == 0) ws[threadIdx.x >> 5] = s;
    __syncthreads();
    if (threadIdx.x == 0) dst[row] = ws[0] + ws[1] + ws[2] + ws[3];
}

// ================= bf16 HMMA GEMM -> bf16 score matrix =================
// 128x256 CTA tile, BK=32, 256 threads = 8 warps (2m x 4n), warp tile 64x64.
// 3-stage cp.async ring. smem rows padded to 80B.
#define ROWB    80
#define SA_STG  (128 * ROWB)   // 10240
#define SB_STG  (256 * ROWB)   // 20480
#define SB_BASE (3 * SA_STG)   // B region starts after 3 A stages
#define SM_TOT  (3 * SA_STG + 3 * SB_STG)  // 92160

__global__ void __launch_bounds__(256, 1) gemm_score_mma() {
    extern __shared__ __align__(128) uint8_t smem[];
    const uint32_t sbA = smem_u32(smem);
    const uint32_t sbB = sbA + SB_BASE;

    const int tid  = threadIdx.x;
    const int lane = tid & 31;
    const int wid  = tid >> 5;
    const int wm   = wid >> 2;          // 0..1
    const int wn   = wid & 3;           // 0..3
    const int bm   = blockIdx.y * 128;  // feature rows
    const int bn   = blockIdx.x * 256;  // memory rows

    // cp.async staging coords
    const int rr = tid >> 2;            // 0..63
    const int kc = tid & 3;             // 16B chunk in 64B (=32 bf16) row
    const __nv_bfloat16* gA = g_abf + (size_t)bm * D_DIM + kc * 8;
    const __nv_bfloat16* gB = g_bbf + (size_t)bn * D_DIM + kc * 8;

    // ldmatrix per-thread offsets
    const int lrow = (lane & 7) + ((lane >> 3) & 1) * 8;  // 0..15
    const int lcol = (lane >> 4) * 8;                     // 0 or 8
    uint32_t aBase[4], bBase[4];
    #pragma unroll
    for (int mf = 0; mf < 4; mf++)
        aBase[mf] = sbA + (wm * 64 + mf * 16 + lrow) * ROWB + lcol * 2;
    #pragma unroll
    for (int np = 0; np < 4; np++)
        bBase[np] = sbB + (wn * 64 + np * 16 + lrow) * ROWB + lcol * 2;

    float acc[4][8][4];
    #pragma unroll
    for (int mf = 0; mf < 4; mf++)
        #pragma unroll
        for (int nf = 0; nf < 8; nf++)
            #pragma unroll
            for (int e = 0; e < 4; e++) acc[mf][nf][e] = 0.0f;

    // stage loader: A 2 chunks/thread, B 4 chunks/thread
    auto load_stage = [&](int kt, int buf) {
        const int koff = kt * 32;  // bf16 elems
        #pragma unroll
        for (int i = 0; i < 2; i++) {
            int r = rr + i * 64;
            CP_ASYNC16(sbA + buf * SA_STG + r * ROWB + kc * 16,
                       gA + (size_t)r * D_DIM + koff);
        }
        #pragma unroll
        for (int i = 0; i < 4; i++) {
            int r = rr + i * 64;
            CP_ASYNC16(sbB + buf * SB_STG + r * ROWB + kc * 16,
                       gB + (size_t)r * D_DIM + koff);
        }
    };

    load_stage(0, 0); CP_COMMIT();
    load_stage(1, 1); CP_COMMIT();

    #pragma unroll 1
    for (int kt = 0; kt < 16; kt++) {
        const int buf = kt % 3;
        CP_WAIT(1);
        __syncthreads();
        if (kt + 2 < 16) load_stage(kt + 2, (kt + 2) % 3);
        CP_COMMIT();

        const uint32_t ao = buf * SA_STG;
        const uint32_t bo = buf * SB_STG;
        #pragma unroll
        for (int ks = 0; ks < 2; ks++) {
            const int ko = ks * 32;  // 16 bf16 = 32 B
            uint32_t af[4][4], bf[4][4];
            #pragma unroll
            for (int mf = 0; mf < 4; mf++)
                LDSM_X4(af[mf][0], af[mf][1], af[mf][2], af[mf][3], aBase[mf] + ao + ko);
            #pragma unroll
            for (int np = 0; np < 4; np++)
                LDSM_X4(bf[np][0], bf[np][1], bf[np][2], bf[np][3], bBase[np] + bo + ko);

            #pragma unroll
            for (int mf = 0; mf < 4; mf++) {
                #pragma unroll
                for (int nf = 0; nf < 8; nf++) {
                    const int np = nf >> 1, o = nf & 1;
                    MMA16816(acc[mf][nf][0], acc[mf][nf][1], acc[mf][nf][2], acc[mf][nf][3],
                             af[mf][0], af[mf][1], af[mf][2], af[mf][3],
                             bf[np][0 + o], bf[np][2 + o]);
                }
            }
        }
    }

    // epilogue: score = m2 - 2*dot, stored bf16
    const int q = lane >> 2, p = lane & 3;
    #pragma unroll
    for (int nf = 0; nf < 8; nf++) {
        const int cg = bn + wn * 64 + nf * 8 + p * 2;
        const float m20 = g_m2[cg], m21 = g_m2[cg + 1];
        #pragma unroll
        for (int mf = 0; mf < 4; mf++) {
            const int rg0 = bm + wm * 64 + mf * 16 + q;
            __nv_bfloat162 s0, s1;
            s0.x = __float2bfloat16(m20 - 2.0f * acc[mf][nf][0]);
            s0.y = __float2bfloat16(m21 - 2.0f * acc[mf][nf][1]);
            s1.x = __float2bfloat16(m20 - 2.0f * acc[mf][nf][2]);
            s1.y = __float2bfloat16(m21 - 2.0f * acc[mf][nf][3]);
            *(__nv_bfloat162*)(g_score + (size_t)rg0 * M_ROWS + cg) = s0;
            *(__nv_bfloat162*)(g_score + (size_t)(rg0 + 8) * M_ROWS + cg) = s1;
        }
    }
}

// ================= top-16 candidates per row (bf16 scores) =================
// 512 threads/row; per-thread top-8 (registers, strict guard), warp-shuffle merge.
__global__ __launch_bounds__(512) void topk_kernel() {
    const int row = blockIdx.x;
    const int tid = threadIdx.x;
    const uint4* sr = (const uint4*)(g_score + (size_t)row * M_ROWS);

    float ld[8];
    int   li[8];
    #pragma unroll
    for (int k = 0; k < 8; k++) { ld[k] = FLT_MAX; li[k] = 0x7fffffff; }

    #pragma unroll 1
    for (int it = 0; it < M_ROWS / (512 * 8); it++) {   // 4 iterations
        const int vi = it * 512 + tid;
        uint4 u = sr[vi];
        float2 f0 = __bfloat1622float2(*(const __nv_bfloat162*)&u.x);
        float2 f1 = __bfloat1622float2(*(const __nv_bfloat162*)&u.y);
        float2 f2 = __bfloat1622float2(*(const __nv_bfloat162*)&u.z);
        float2 f3 = __bfloat1622float2(*(const __nv_bfloat162*)&u.w);
        float v[8] = {f0.x, f0.y, f1.x, f1.y, f2.x, f2.y, f3.x, f3.y};
        float m8 = fminf(fminf(fminf(v[0], v[1]), fminf(v[2], v[3])),
                         fminf(fminf(v[4], v[5]), fminf(v[6], v[7])));
        if (m8 < ld[7]) {
            const int base = vi * 8;
            #pragma unroll
            for (int e = 0; e < 8; e++) {
                float x = v[e];
                if (x < ld[7]) {
                    int xi = base + e;
                    #pragma unroll
                    for (int k = 0; k < 8; k++) {
                        bool lt = (x < ld[k]) || (x == ld[k] && xi < li[k]);
                        float td = lt ? ld[k] : x;  int ti = lt ? li[k] : xi;
                        ld[k] = lt ? x : ld[k];     li[k] = lt ? xi : li[k];
                        x = td; xi = ti;
                    }
                }
            }
        }
    }

    __shared__ float wd[16];
    __shared__ int   wi[16];
    __shared__ float fd;
    __shared__ int   fi;

    #pragma unroll 1
    for (int r = 0; r < K_CAND; r++) {
        // warp-level lexicographic argmin of heads
        float d = ld[0]; int ix = li[0];
        #pragma unroll
        for (int o = 16; o; o >>= 1) {
            float d2 = __shfl_down_sync(0xffffffffu, d, o);
            int   i2 = __shfl_down_sync(0xffffffffu, ix, o);
            if (d2 < d || (d2 == d && i2 < ix)) { d = d2; ix = i2; }
        }
        if ((tid & 31) == 0) { wd[tid >> 5] = d; wi[tid >> 5] = ix; }
        __syncthreads();
        if (tid == 0) {
            float bd = wd[0]; int bi = wi[0];
            #pragma unroll
            for (int w = 1; w < 16; w++)
                if (wd[w] < bd || (wd[w] == bd && wi[w] < bi)) { bd = wd[w]; bi = wi[w]; }
            fd = bd; fi = bi;
            g_cand[(size_t)row * K_CAND + r] = bi;
        }
        __syncthreads();
        if (ld[0] == fd && li[0] == fi) {
            #pragma unroll
            for (int k = 0; k < 7; k++) { ld[k] = ld[k + 1]; li[k] = li[k + 1]; }
            ld[7] = FLT_MAX; li[7] = 0x7fffffff;
        }
        __syncthreads();
    }
}

// ================= exact rerank of 16 candidates =================
__global__ __launch_bounds__(512) void rerank_kernel(const float* __restrict__ feat,
                                                     const float* __restrict__ mem,
                                                     float* __restrict__ out) {
    const int row = blockIdx.x;
    const int wid = threadIdx.x >> 5;
    const int lid = threadIdx.x & 31;

    __shared__ float sd[K_CAND];
    __shared__ int   si[K_CAND];

    int cand = g_cand[(size_t)row * K_CAND + wid];
    const float4* f4 = (const float4*)(feat + (size_t)row * D_DIM);
    const float4* m4 = (const float4*)(mem + (size_t)cand * D_DIM);
    float acc = 0.0f;
    #pragma unroll
    for (int i = 0; i < 4; i++) {
        float4 a = f4[lid + i * 32];
        float4 b = m4[lid + i * 32];
        acc += a.x * b.x + a.y * b.y + a.z * b.z + a.w * b.w;
    }
    #pragma unroll
    for (int o = 16; o; o >>= 1) acc += __shfl_down_sync(0xffffffffu, acc, o);
    if (lid == 0) {
        float d2 = g_x2[row] + g_m2[cand] - 2.0f * acc;
        sd[wid] = sqrtf(fmaxf(d2, 0.0f) + EPSF);
        si[wid] = cand;
    }
    __syncthreads();

    if (threadIdx.x == 0) {
        for (int i = 1; i < K_CAND; i++) {
            float d = sd[i]; int ix = si[i];
            int j = i - 1;
            while (j >= 0 && (sd[j] > d || (sd[j] == d && si[j] > ix))) {
                sd[j + 1] = sd[j]; si[j + 1] = si[j]; j--;
            }
            sd[j + 1] = d; si[j + 1] = ix;
        }
        float* knn_out = out + 2 * (size_t)N_ROWS * D_DIM + (size_t)row * K_TOP;
        float sum = 0.0f;
        #pragma unroll
        for (int k = 0; k < K_TOP; k++) { knn_out[k] = sd[k]; sum += sd[k]; }
        g_idx0[row] = si[0];
        float mean = sum * 0.1f;
        g_mean[row] = mean;
        atomicMin(&g_dmin_bits, __float_as_int(mean));
        atomicMax(&g_dmax_bits, __float_as_int(mean));
    }
}

// ================= final epilogue =================
__global__ __launch_bounds__(128) void final_kernel(const float* __restrict__ feat,
                                                    const float* __restrict__ mem,
                                                    const float* __restrict__ iscale,
                                                    const float* __restrict__ dscale,
                                                    float* __restrict__ out) {
    const int row = blockIdx.x;
    const int t = threadIdx.x;

    const float* knn = out + 2 * (size_t)N_ROWS * D_DIM;
    float norm = knn[(size_t)row * K_TOP] + EPSF;
    float inv = 1.0f / norm;
    int idx0 = g_idx0[row];

    float4 f  = *(const float4*)(feat + (size_t)row * D_DIM + t * 4);
    float4 nb = *(const float4*)(mem + (size_t)idx0 * D_DIM + t * 4);

    float v0 = fabsf((f.x - nb.x) * inv);
    float v1 = fabsf((f.y - nb.y) * inv);
    float v2 = fabsf((f.z - nb.z) * inv);
    float v3 = fabsf((f.w - nb.w) * inv);

    float mn = fminf(fminf(v0, v1), fminf(v2, v3));
    float mx = fmaxf(fmaxf(v0, v1), fmaxf(v2, v3));
    #pragma unroll
    for (int o = 16; o; o >>= 1) {
        mn = fminf(mn, __shfl_down_sync(0xffffffffu, mn, o));
        mx = fmaxf(mx, __shfl_down_sync(0xffffffffu, mx, o));
    }
    __shared__ float smn[4], smx[4];
    __shared__ float bmn, bmx;
    if ((t & 31) == 0) { smn[t >> 5] = mn; smx[t >> 5] = mx; }
    __syncthreads();
    if (t == 0) {
        bmn = fminf(fminf(smn[0], smn[1]), fminf(smn[2], smn[3]));
        bmx = fmaxf(fmaxf(smx[0], smx[1]), fmaxf(smx[2], smx[3]));
    }
    __syncthreads();
    float inf_min = bmn;
    float rinv = 1.0f / (bmx - inf_min + EPSF);

    float dmin = __int_as_float(g_dmin_bits);
    float dmax = __int_as_float(g_dmax_bits);
    float dn = (g_mean[row] - dmin) / (dmax - dmin + EPSF);

    float si = iscale[0], sd = dscale[0];
    float base = sd * dn - 0.5f;

    *(float4*)(out + (size_t)row * D_DIM + t * 4) = make_float4(v0, v1, v2, v3);

    float4 ns;
    float c;
    c = si * ((v0 - inf_min) * rinv) + base; ns.x = 0.01f + 0.49f / (1.0f + expf(-c));
    c = si * ((v1 - inf_min) * rinv) + base; ns.y = 0.01f + 0.49f / (1.0f + expf(-c));
    c = si * ((v2 - inf_min) * rinv) + base; ns.z = 0.01f + 0.49f / (1.0f + expf(-c));
    c = si * ((v3 - inf_min) * rinv) + base; ns.w = 0.01f + 0.49f / (1.0f + expf(-c));
    *(float4*)(out + (size_t)N_ROWS * D_DIM + (size_t)row * D_DIM + t * 4) = ns;
}

// ================= launch =================
extern "C" void kernel_launch(void* const* d_in, const int* in_sizes, int n_in,
                              void* d_out, int out_size) {
    const float* feat = (const float*)d_in[0];
    const float* mem  = (const float*)d_in[1];
    const float* isc  = (const float*)d_in[2];
    const float* dsc  = (const float*)d_in[3];
    float* out = (float*)d_out;

    cudaFuncSetAttribute(gemm_score_mma, cudaFuncAttributeMaxDynamicSharedMemorySize, SM_TOT);

    init_kernel<<<1, 1>>>();
    prep_bf16<<<(M_ROWS * D_DIM + 255) / 256, 256>>>(feat, mem);
    rowsumsq<<<N_ROWS, 128>>>(feat, 0);
    rowsumsq<<<M_ROWS, 128>>>(mem, 1);

    dim3 ggrid(M_ROWS / 256, N_ROWS / 128);  // (64, 64)
    gemm_score_mma<<<ggrid, 256, SM_TOT>>>();

    topk_kernel<<<N_ROWS, 512>>>();
    rerank_kernel<<<N_ROWS, 512>>>(feat, mem, out);
    final_kernel<<<N_ROWS, 128>>>(feat, mem, isc, dsc, out);
}